// round 1
// baseline (speedup 1.0000x reference)
#include <cuda_runtime.h>
#include <cuda_bf16.h>
#include <cstdint>

#define B_ 128
#define T_ 2048
#define DP_ 256
#define DQ_ 256
#define DO_ 256
#define TT 64        // token tile in kernel B
#define QSTR 132     // Q_sh row stride in 32-bit words (264 bf16)

__device__ float g_gpr[B_ * DO_];    // Gp + b_p_r + b_q  per (b,d)
__device__ float g_alpha[B_ * T_];   // alpha_raw then softmax result

__device__ __forceinline__ float fast_tanh(float x) {
    float y;
    asm("tanh.approx.f32 %0, %1;" : "=f"(y) : "f"(x));
    return y;
}

// ---------------- Kernel A: gpr[b,d] = cat(p,h)[b] . W_p_r[d] + b_p_r[d] + b_q[d]
__global__ void kA_gpr(const float* __restrict__ input_p,
                       const float* __restrict__ h_tm1,
                       const float* __restrict__ W_p_r,
                       const float* __restrict__ b_p_r,
                       const float* __restrict__ b_q) {
    __shared__ float ph[DP_ + DO_];
    int b = blockIdx.x, tid = threadIdx.x;
    ph[tid]       = input_p[b * DP_ + tid];
    ph[DP_ + tid] = h_tm1[b * DO_ + tid];
    __syncthreads();
    int d = tid;
    const float4* Wrow = reinterpret_cast<const float4*>(W_p_r + (size_t)d * (DP_ + DO_));
    float a0 = 0.f, a1 = 0.f, a2 = 0.f, a3 = 0.f;
#pragma unroll 8
    for (int k4 = 0; k4 < (DP_ + DO_) / 4; ++k4) {
        float4 wv = Wrow[k4];
        a0 += wv.x * ph[k4 * 4 + 0];
        a1 += wv.y * ph[k4 * 4 + 1];
        a2 += wv.z * ph[k4 * 4 + 2];
        a3 += wv.w * ph[k4 * 4 + 3];
    }
    g_gpr[b * DO_ + d] = b_p_r[d] + b_q[d] + ((a0 + a1) + (a2 + a3));
}

// ---------------- Kernel B: alpha_raw[b,t] = sum_d w[d]*tanh(gpr[b,d] + (Q@W^T)[t,d]) + match_b
// One block per batch b. W_q resident in SMEM as bf16 (swizzled), Q tiles of 64 tokens.
__global__ __launch_bounds__(256, 1)
void kB_alpha(const float* __restrict__ input_q,
              const float* __restrict__ W_q,
              const float* __restrict__ wvec,
              const float* __restrict__ match_b) {
    extern __shared__ uint32_t sh[];
    uint32_t* Wsh = sh;                         // 256 rows * 128 words (bf16x2), swizzled
    uint32_t* Qsh = sh + 256 * 128;             // 64 rows * 132 words (264 bf16, padded)
    float* gpr_sh   = reinterpret_cast<float*>(Qsh + TT * QSTR);
    float* w_sh     = gpr_sh + DO_;
    float* alpha_sh = w_sh + DO_;

    int b    = blockIdx.x;
    int tid  = threadIdx.x;
    int lane = tid & 31, wid = tid >> 5;
    int warp_m = wid & 3;       // 4 warps over 64 rows (16 each)
    int warp_n = wid >> 2;      // 2 warps over 256 cols (128 each)

    // Load W_q (fp32) -> bf16 SMEM, 16B-chunk XOR swizzle for conflict-free ldmatrix
    for (int i = tid; i < 256 * 128; i += 256) {
        int n = i >> 7, kw = i & 127;
        float2 f = reinterpret_cast<const float2*>(W_q)[n * 128 + kw];
        __nv_bfloat162 h = __floats2bfloat162_rn(f.x, f.y);
        int chunk = kw >> 2;
        int phys  = chunk ^ (n & 7);
        Wsh[n * 128 + phys * 4 + (kw & 3)] = *reinterpret_cast<uint32_t*>(&h);
    }
    if (tid < DO_) {
        gpr_sh[tid] = g_gpr[b * DO_ + tid];
        w_sh[tid]   = wvec[tid];
    }
    __syncthreads();

    const float  mb    = match_b[0];
    const float2* qbase = reinterpret_cast<const float2*>(input_q + (size_t)b * T_ * DQ_);

    for (int t0 = 0; t0 < T_; t0 += TT) {
        if (tid < TT) alpha_sh[tid] = 0.f;
        // Load Q tile (fp32 -> bf16)
        for (int i = tid; i < TT * 128; i += 256) {
            int row = i >> 7, kw = i & 127;
            float2 f = qbase[(size_t)(t0 + row) * (DQ_ / 2) + kw];
            __nv_bfloat162 h = __floats2bfloat162_rn(f.x, f.y);
            Qsh[row * QSTR + kw] = *reinterpret_cast<uint32_t*>(&h);
        }
        __syncthreads();

        float c[16][4];
#pragma unroll
        for (int nt = 0; nt < 16; ++nt) {
            c[nt][0] = c[nt][1] = c[nt][2] = c[nt][3] = 0.f;
        }

#pragma unroll 2
        for (int kc = 0; kc < 16; ++kc) {
            // A fragment (16x16) via ldmatrix x4
            int arow  = warp_m * 16 + (lane & 15);
            int acol2 = kc * 8 + ((lane & 16) ? 4 : 0);  // word offset
            uint32_t aaddr = (uint32_t)__cvta_generic_to_shared(&Qsh[arow * QSTR + acol2]);
            uint32_t a0, a1, a2, a3;
            asm volatile("ldmatrix.sync.aligned.m8n8.x4.shared.b16 {%0,%1,%2,%3}, [%4];"
                         : "=r"(a0), "=r"(a1), "=r"(a2), "=r"(a3) : "r"(aaddr));
#pragma unroll
            for (int np = 0; np < 8; ++np) {  // pairs of 8-wide n-tiles
                int n0    = warp_n * 128 + np * 16;
                int row   = n0 + (lane & 7) + ((lane & 16) ? 8 : 0);
                int chunk = kc * 2 + ((lane & 8) ? 1 : 0);
                int phys  = chunk ^ (row & 7);
                uint32_t baddr = (uint32_t)__cvta_generic_to_shared(&Wsh[row * 128 + phys * 4]);
                uint32_t b0, b1, b2, b3;
                asm volatile("ldmatrix.sync.aligned.m8n8.x4.shared.b16 {%0,%1,%2,%3}, [%4];"
                             : "=r"(b0), "=r"(b1), "=r"(b2), "=r"(b3) : "r"(baddr));
                asm volatile(
                    "mma.sync.aligned.m16n8k16.row.col.f32.bf16.bf16.f32 "
                    "{%0,%1,%2,%3}, {%4,%5,%6,%7}, {%8,%9}, {%0,%1,%2,%3};"
                    : "+f"(c[np * 2][0]), "+f"(c[np * 2][1]), "+f"(c[np * 2][2]), "+f"(c[np * 2][3])
                    : "r"(a0), "r"(a1), "r"(a2), "r"(a3), "r"(b0), "r"(b1));
                asm volatile(
                    "mma.sync.aligned.m16n8k16.row.col.f32.bf16.bf16.f32 "
                    "{%0,%1,%2,%3}, {%4,%5,%6,%7}, {%8,%9}, {%0,%1,%2,%3};"
                    : "+f"(c[np * 2 + 1][0]), "+f"(c[np * 2 + 1][1]), "+f"(c[np * 2 + 1][2]), "+f"(c[np * 2 + 1][3])
                    : "r"(a0), "r"(a1), "r"(a2), "r"(a3), "r"(b2), "r"(b3));
            }
        }

        // Epilogue: tanh + dot with w, reduce per token row
        float p0 = 0.f, p1 = 0.f;
#pragma unroll
        for (int nt = 0; nt < 16; ++nt) {
            int n = warp_n * 128 + nt * 8 + (lane & 3) * 2;
            float g0 = gpr_sh[n], g1 = gpr_sh[n + 1];
            float w0 = w_sh[n],   w1 = w_sh[n + 1];
            p0 += w0 * fast_tanh(c[nt][0] + g0) + w1 * fast_tanh(c[nt][1] + g1);
            p1 += w0 * fast_tanh(c[nt][2] + g0) + w1 * fast_tanh(c[nt][3] + g1);
        }
        int row0 = warp_m * 16 + (lane >> 2);
        atomicAdd(&alpha_sh[row0], p0);
        atomicAdd(&alpha_sh[row0 + 8], p1);
        __syncthreads();
        if (tid < TT) g_alpha[b * T_ + t0 + tid] = alpha_sh[tid] + mb;
        __syncthreads();
    }
}

// ---------------- Kernel C: masked softmax over T (in-place on g_alpha)
__global__ void kC_softmax(const int* __restrict__ mask_q) {
    __shared__ float red_max[8];
    __shared__ float red_sum[8];
    int b = blockIdx.x, tid = threadIdx.x;
    int lane = tid & 31, wid = tid >> 5;

    float x[8], m[8];
    float mx = -1e30f;
#pragma unroll
    for (int i = 0; i < 8; ++i) {
        int t = tid + i * 256;
        float a = g_alpha[b * T_ + t];
        m[i] = (float)mask_q[b * T_ + t];
        a = fminf(fmaxf(a, -15.f), 15.f) * m[i];
        x[i] = a;
        mx = fmaxf(mx, a);
    }
#pragma unroll
    for (int o = 16; o; o >>= 1) mx = fmaxf(mx, __shfl_xor_sync(0xffffffffu, mx, o));
    if (lane == 0) red_max[wid] = mx;
    __syncthreads();
    float bm = red_max[0];
#pragma unroll
    for (int i = 1; i < 8; ++i) bm = fmaxf(bm, red_max[i]);

    float e[8];
    float s = 0.f;
#pragma unroll
    for (int i = 0; i < 8; ++i) {
        e[i] = expf(x[i] - bm) * m[i];
        s += e[i];
    }
#pragma unroll
    for (int o = 16; o; o >>= 1) s += __shfl_xor_sync(0xffffffffu, s, o);
    if (lane == 0) red_sum[wid] = s;
    __syncthreads();
    float tot = 0.f;
#pragma unroll
    for (int i = 0; i < 8; ++i) tot += red_sum[i];
    float inv = 1.f / (tot + 1e-6f);
#pragma unroll
    for (int i = 0; i < 8; ++i) {
        int t = tid + i * 256;
        g_alpha[b * T_ + t] = e[i] * inv;
    }
}

// ---------------- Kernel D: z[b,d] = sum_t alpha[b,t]*q[b,t,d];  out = [input_p | z]
__global__ void kD_z(const float* __restrict__ input_q,
                     const float* __restrict__ input_p,
                     float* __restrict__ out) {
    __shared__ float alpha_sh[T_];
    __shared__ float partial[8][32];
    int j = blockIdx.x, b = blockIdx.y;
    int tid = threadIdx.x, lane = tid & 31, wid = tid >> 5;

    for (int i = tid; i < T_; i += 256) alpha_sh[i] = g_alpha[b * T_ + i];
    if (tid < 32) out[b * 512 + j * 32 + tid] = input_p[b * 256 + j * 32 + tid];
    __syncthreads();

    const float* qb = input_q + (size_t)b * T_ * 256 + j * 32 + lane;
    float acc = 0.f;
#pragma unroll 4
    for (int t = wid; t < T_; t += 8) {
        acc += alpha_sh[t] * qb[(size_t)t * 256];
    }
    partial[wid][lane] = acc;
    __syncthreads();
    if (wid == 0) {
        float s = acc;
#pragma unroll
        for (int w = 1; w < 8; ++w) s += partial[w][lane];
        out[b * 512 + 256 + j * 32 + lane] = s;
    }
}

extern "C" void kernel_launch(void* const* d_in, const int* in_sizes, int n_in,
                              void* d_out, int out_size) {
    const float* input_p = (const float*)d_in[0];
    // d_in[1] = mask_p (unused by the reference)
    const float* input_q = (const float*)d_in[2];
    const int*   mask_q  = (const int*)d_in[3];
    const float* h_tm1   = (const float*)d_in[4];
    const float* W_p_r   = (const float*)d_in[5];
    const float* b_p_r   = (const float*)d_in[6];
    const float* W_q     = (const float*)d_in[7];
    const float* b_q     = (const float*)d_in[8];
    const float* wv      = (const float*)d_in[9];
    const float* match_b = (const float*)d_in[10];
    float* out = (float*)d_out;

    kA_gpr<<<B_, 256>>>(input_p, h_tm1, W_p_r, b_p_r, b_q);

    size_t smemB = (size_t)(256 * 128 + TT * QSTR) * 4 + (DO_ + DO_ + TT) * 4;
    cudaFuncSetAttribute(kB_alpha, cudaFuncAttributeMaxDynamicSharedMemorySize, (int)smemB);
    kB_alpha<<<B_, 256, smemB>>>(input_q, W_q, wv, match_b);

    kC_softmax<<<B_, 256>>>(mask_q);

    kD_z<<<dim3(8, B_), 256>>>(input_q, input_p, out);
}

// round 2
// speedup vs baseline: 1.4128x; 1.4128x over previous
#include <cuda_runtime.h>
#include <cuda_bf16.h>
#include <cstdint>

#define B_ 128
#define T_ 2048
#define DP_ 256
#define DQ_ 256
#define DO_ 256
#define TT 64          // token tile
#define NTILES (T_ / TT)
#define QSTR 132       // Q smem row stride in 32-bit words

__device__ float g_gpr[B_ * DO_];

__device__ __forceinline__ float fast_tanh(float x) {
    float y;
    asm("tanh.approx.f32 %0, %1;" : "=f"(y) : "f"(x));
    return y;
}

// ---------------- Kernel A: gpr[b,d] = cat(p,h)[b] . W_p_r[d] + b_p_r[d] + b_q[d]
__global__ void kA_gpr(const float* __restrict__ input_p,
                       const float* __restrict__ h_tm1,
                       const float* __restrict__ W_p_r,
                       const float* __restrict__ b_p_r,
                       const float* __restrict__ b_q) {
    __shared__ float ph[DP_ + DO_];
    int b = blockIdx.x, tid = threadIdx.x;
    ph[tid]       = input_p[b * DP_ + tid];
    ph[DP_ + tid] = h_tm1[b * DO_ + tid];
    __syncthreads();
    int d = tid;
    const float4* Wrow = reinterpret_cast<const float4*>(W_p_r + (size_t)d * (DP_ + DO_));
    float a0 = 0.f, a1 = 0.f, a2 = 0.f, a3 = 0.f;
#pragma unroll 8
    for (int k4 = 0; k4 < (DP_ + DO_) / 4; ++k4) {
        float4 wv = Wrow[k4];
        a0 += wv.x * ph[k4 * 4 + 0];
        a1 += wv.y * ph[k4 * 4 + 1];
        a2 += wv.z * ph[k4 * 4 + 2];
        a3 += wv.w * ph[k4 * 4 + 3];
    }
    g_gpr[b * DO_ + d] = b_p_r[d] + b_q[d] + ((a0 + a1) + (a2 + a3));
}

// ---------------- Fused kernel: GEMM + tanh·w + online softmax + z, one block per batch
// smem word layout:
//   Wsh   : [0, 32768)                256 rows x 128 words, XOR-swizzled bf16x2
//   Qsh0  : [32768, 32768+8448)       64 rows x 132 words
//   Qsh1  : [+8448)
//   gpr_sh: 256 f, w_sh: 256 f, e_sh: 64 f, alpha_sh: 64 f, red: 4 f
__global__ __launch_bounds__(256, 1)
void kFused(const float* __restrict__ input_q,
            const float* __restrict__ W_q,
            const float* __restrict__ wvec,
            const float* __restrict__ match_b,
            const int* __restrict__ mask_q,
            const float* __restrict__ input_p,
            float* __restrict__ out) {
    extern __shared__ uint32_t sh[];
    uint32_t* Wsh  = sh;
    uint32_t* Qsh0 = sh + 32768;
    uint32_t* Qsh1 = Qsh0 + TT * QSTR;
    float* gpr_sh   = reinterpret_cast<float*>(Qsh1 + TT * QSTR);
    float* w_sh     = gpr_sh + DO_;
    float* e_sh     = w_sh + DO_;
    float* alpha_sh = e_sh + TT;
    float* red      = alpha_sh + TT;   // [0]=wmax0 [1]=wmax1 [2]=wsum0 [3]=wsum1

    int b    = blockIdx.x;
    int tid  = threadIdx.x;
    int lane = tid & 31, wid = tid >> 5;
    int warp_m = wid & 1;        // 2 warps over 64 rows (32 each)
    int warp_n = wid >> 1;       // 4 warps over 256 cols (64 each)

    // ---- Load W_q (fp32) -> bf16 SMEM with 16B-chunk XOR swizzle
    for (int i = tid; i < 256 * 128; i += 256) {
        int n = i >> 7, kw = i & 127;
        float2 f = reinterpret_cast<const float2*>(W_q)[n * 128 + kw];
        __nv_bfloat162 h = __floats2bfloat162_rn(f.x, f.y);
        int chunk = kw >> 2;
        int phys  = chunk ^ (n & 7);
        Wsh[n * 128 + phys * 4 + (kw & 3)] = *reinterpret_cast<uint32_t*>(&h);
    }
    if (tid < DO_) {
        gpr_sh[tid] = g_gpr[b * DO_ + tid];
        w_sh[tid]   = wvec[tid];
    }
    if (tid < TT) alpha_sh[tid] = 0.f;

    const float   mb    = match_b[0];
    const float4* qb4   = reinterpret_cast<const float4*>(input_q + (size_t)b * T_ * DQ_);
    const int*    mqb   = mask_q + (size_t)b * T_;

    // ---- Preload tile 0
    float4 pf[16];
#pragma unroll
    for (int j = 0; j < 16; ++j) {
        int idx = tid + j * 256;                  // float4 index within tile
        pf[j] = qb4[idx];                         // rows 0..63 of tile 0
    }
#pragma unroll
    for (int j = 0; j < 16; ++j) {
        int idx = tid + j * 256;
        int row = idx >> 6, c4 = idx & 63;
        __nv_bfloat162 h0 = __floats2bfloat162_rn(pf[j].x, pf[j].y);
        __nv_bfloat162 h1 = __floats2bfloat162_rn(pf[j].z, pf[j].w);
        Qsh0[row * QSTR + c4 * 2]     = *reinterpret_cast<uint32_t*>(&h0);
        Qsh0[row * QSTR + c4 * 2 + 1] = *reinterpret_cast<uint32_t*>(&h1);
    }
    __syncthreads();

    float M = -1e30f, S = 0.f, z = 0.f;   // online-softmax state (z: this thread owns dim d=tid)

    for (int it = 0; it < NTILES; ++it) {
        uint32_t* Qcur = (it & 1) ? Qsh1 : Qsh0;
        uint32_t* Qnxt = (it & 1) ? Qsh0 : Qsh1;
        int t0 = it * TT;

        // ---- Prefetch next tile into registers (LDGs in flight during MMA)
        bool has_next = (it + 1 < NTILES);
        if (has_next) {
            const float4* src = qb4 + (size_t)(t0 + TT) * 64;
#pragma unroll
            for (int j = 0; j < 16; ++j) pf[j] = src[tid + j * 256];
        }

        // ---- MMA: C[64 x 256] = Qtile @ W^T, warp tile m32 x n64
        float c[16][4];
#pragma unroll
        for (int q = 0; q < 16; ++q) { c[q][0] = c[q][1] = c[q][2] = c[q][3] = 0.f; }

#pragma unroll 4
        for (int kc = 0; kc < 16; ++kc) {
            uint32_t a[2][4];
#pragma unroll
            for (int mt = 0; mt < 2; ++mt) {
                int arow = warp_m * 32 + mt * 16 + (lane & 15);
                int acol = kc * 8 + ((lane & 16) ? 4 : 0);
                uint32_t aaddr = (uint32_t)__cvta_generic_to_shared(&Qcur[arow * QSTR + acol]);
                asm volatile("ldmatrix.sync.aligned.m8n8.x4.shared.b16 {%0,%1,%2,%3}, [%4];"
                             : "=r"(a[mt][0]), "=r"(a[mt][1]), "=r"(a[mt][2]), "=r"(a[mt][3])
                             : "r"(aaddr));
            }
#pragma unroll
            for (int np = 0; np < 4; ++np) {
                int n0    = warp_n * 64 + np * 16;
                int row   = n0 + (lane & 7) + ((lane & 16) ? 8 : 0);
                int chunk = kc * 2 + ((lane & 8) ? 1 : 0);
                int phys  = chunk ^ (row & 7);
                uint32_t baddr = (uint32_t)__cvta_generic_to_shared(&Wsh[row * 128 + phys * 4]);
                uint32_t b0, b1, b2, b3;
                asm volatile("ldmatrix.sync.aligned.m8n8.x4.shared.b16 {%0,%1,%2,%3}, [%4];"
                             : "=r"(b0), "=r"(b1), "=r"(b2), "=r"(b3) : "r"(baddr));
#pragma unroll
                for (int mt = 0; mt < 2; ++mt) {
                    float* c0 = c[mt * 8 + np * 2];
                    float* c1 = c[mt * 8 + np * 2 + 1];
                    asm volatile(
                        "mma.sync.aligned.m16n8k16.row.col.f32.bf16.bf16.f32 "
                        "{%0,%1,%2,%3}, {%4,%5,%6,%7}, {%8,%9}, {%0,%1,%2,%3};"
                        : "+f"(c0[0]), "+f"(c0[1]), "+f"(c0[2]), "+f"(c0[3])
                        : "r"(a[mt][0]), "r"(a[mt][1]), "r"(a[mt][2]), "r"(a[mt][3]),
                          "r"(b0), "r"(b1));
                    asm volatile(
                        "mma.sync.aligned.m16n8k16.row.col.f32.bf16.bf16.f32 "
                        "{%0,%1,%2,%3}, {%4,%5,%6,%7}, {%8,%9}, {%0,%1,%2,%3};"
                        : "+f"(c1[0]), "+f"(c1[1]), "+f"(c1[2]), "+f"(c1[3])
                        : "r"(a[mt][0]), "r"(a[mt][1]), "r"(a[mt][2]), "r"(a[mt][3]),
                          "r"(b2), "r"(b3));
                }
            }
        }

        // ---- Epilogue: tanh + dot(w), per-row partial sums -> alpha_sh (zeroed previously)
#pragma unroll
        for (int mt = 0; mt < 2; ++mt) {
            float p0 = 0.f, p1 = 0.f;
#pragma unroll
            for (int j = 0; j < 8; ++j) {
                int n = warp_n * 64 + j * 8 + (lane & 3) * 2;
                float g0 = gpr_sh[n], g1 = gpr_sh[n + 1];
                float w0 = w_sh[n],   w1 = w_sh[n + 1];
                float* cc = c[mt * 8 + j];
                p0 += w0 * fast_tanh(cc[0] + g0) + w1 * fast_tanh(cc[1] + g1);
                p1 += w0 * fast_tanh(cc[2] + g0) + w1 * fast_tanh(cc[3] + g1);
            }
            int row0 = warp_m * 32 + mt * 16 + (lane >> 2);
            atomicAdd(&alpha_sh[row0], p0);
            atomicAdd(&alpha_sh[row0 + 8], p1);
        }
        __syncthreads();   // S1: alpha complete, Qcur reads (MMA) done

        // ---- Online softmax stage 1: x = clip(raw+mb)*m, tile max
        float x = 0.f, mflt = 0.f;
        if (tid < TT) {
            float raw = alpha_sh[tid] + mb;
            mflt = (float)mqb[t0 + tid];
            x = fminf(fmaxf(raw, -15.f), 15.f) * mflt;
            float wmx = x;
#pragma unroll
            for (int o = 16; o; o >>= 1) wmx = fmaxf(wmx, __shfl_xor_sync(0xffffffffu, wmx, o));
            if (lane == 0) red[wid] = wmx;
        }
        __syncthreads();   // S2: red[0],red[1] ready

        float tmax  = fmaxf(red[0], red[1]);
        float Mnew  = fmaxf(M, tmax);
        float scale = expf(M - Mnew);
        M = Mnew;

        // ---- stage 2: e values + tile sum; also zero alpha_sh for next tile
        if (tid < TT) {
            float e = expf(x - Mnew) * mflt;
            e_sh[tid] = e;
            alpha_sh[tid] = 0.f;
            float wsm = e;
#pragma unroll
            for (int o = 16; o; o >>= 1) wsm += __shfl_xor_sync(0xffffffffu, wsm, o);
            if (lane == 0) red[2 + wid] = wsm;
        }
        __syncthreads();   // S3: e_sh, red[2..3] ready

        S = S * scale + (red[2] + red[3]);

        // ---- z update: z_d = z_d*scale + sum_t e[t] * Q[t,d]  (from bf16 tile in smem)
        {
            float acc = 0.f;
            int word = tid >> 1, hi = tid & 1;
#pragma unroll 8
            for (int t = 0; t < TT; ++t) {
                uint32_t qw = Qcur[t * QSTR + word];
                __nv_bfloat162 h2 = *reinterpret_cast<__nv_bfloat162*>(&qw);
                float qv = hi ? __bfloat162float(__high2bfloat16(h2))
                              : __bfloat162float(__low2bfloat16(h2));
                acc += e_sh[t] * qv;
            }
            z = z * scale + acc;
        }

        // ---- Store prefetched tile into the other buffer
        if (has_next) {
#pragma unroll
            for (int j = 0; j < 16; ++j) {
                int idx = tid + j * 256;
                int row = idx >> 6, c4 = idx & 63;
                __nv_bfloat162 h0 = __floats2bfloat162_rn(pf[j].x, pf[j].y);
                __nv_bfloat162 h1 = __floats2bfloat162_rn(pf[j].z, pf[j].w);
                Qnxt[row * QSTR + c4 * 2]     = *reinterpret_cast<uint32_t*>(&h0);
                Qnxt[row * QSTR + c4 * 2 + 1] = *reinterpret_cast<uint32_t*>(&h1);
            }
        }
        __syncthreads();   // S4: next buffer ready, e_sh free
    }

    // ---- Finalize: out = [input_p | z/(S+1e-6)]
    float inv = 1.f / (S + 1e-6f);
    out[b * (DP_ + DQ_) + tid]       = input_p[b * DP_ + tid];
    out[b * (DP_ + DQ_) + DP_ + tid] = z * inv;
}

extern "C" void kernel_launch(void* const* d_in, const int* in_sizes, int n_in,
                              void* d_out, int out_size) {
    const float* input_p = (const float*)d_in[0];
    // d_in[1] = mask_p (unused by the reference)
    const float* input_q = (const float*)d_in[2];
    const int*   mask_q  = (const int*)d_in[3];
    const float* h_tm1   = (const float*)d_in[4];
    const float* W_p_r   = (const float*)d_in[5];
    const float* b_p_r   = (const float*)d_in[6];
    const float* W_q     = (const float*)d_in[7];
    const float* b_q     = (const float*)d_in[8];
    const float* wv      = (const float*)d_in[9];
    const float* match_b = (const float*)d_in[10];
    float* out = (float*)d_out;

    kA_gpr<<<B_, 256>>>(input_p, h_tm1, W_p_r, b_p_r, b_q);

    size_t smemF = (size_t)(32768 + 2 * TT * QSTR) * 4 +
                   (DO_ + DO_ + TT + TT + 4) * 4;
    cudaFuncSetAttribute(kFused, cudaFuncAttributeMaxDynamicSharedMemorySize, (int)smemF);
    kFused<<<B_, 256, smemF>>>(input_q, W_q, wv, match_b, mask_q, input_p, out);
}

// round 3
// speedup vs baseline: 1.7693x; 1.2524x over previous
#include <cuda_runtime.h>
#include <cuda_bf16.h>
#include <cstdint>

#define B_ 128
#define T_ 2048
#define DP_ 256
#define DQ_ 256
#define DO_ 256
#define TT 64          // token tile
#define NTILES (T_ / TT)
#define QSTR 132       // Q smem row stride in 32-bit words
#define NTHR 512

__device__ float g_gpr[B_ * DO_];

__device__ __forceinline__ float fast_tanh(float x) {
    float y;
    asm("tanh.approx.f32 %0, %1;" : "=f"(y) : "f"(x));
    return y;
}

// ---------------- Kernel A: gpr[b,d] = cat(p,h)[b] . W_p_r[d] + b_p_r[d] + b_q[d]
__global__ void kA_gpr(const float* __restrict__ input_p,
                       const float* __restrict__ h_tm1,
                       const float* __restrict__ W_p_r,
                       const float* __restrict__ b_p_r,
                       const float* __restrict__ b_q) {
    __shared__ float ph[DP_ + DO_];
    int b = blockIdx.x, tid = threadIdx.x;
    ph[tid]       = input_p[b * DP_ + tid];
    ph[DP_ + tid] = h_tm1[b * DO_ + tid];
    __syncthreads();
    int d = tid;
    const float4* Wrow = reinterpret_cast<const float4*>(W_p_r + (size_t)d * (DP_ + DO_));
    float a0 = 0.f, a1 = 0.f, a2 = 0.f, a3 = 0.f;
#pragma unroll 8
    for (int k4 = 0; k4 < (DP_ + DO_) / 4; ++k4) {
        float4 wv = Wrow[k4];
        a0 += wv.x * ph[k4 * 4 + 0];
        a1 += wv.y * ph[k4 * 4 + 1];
        a2 += wv.z * ph[k4 * 4 + 2];
        a3 += wv.w * ph[k4 * 4 + 3];
    }
    g_gpr[b * DO_ + d] = b_p_r[d] + b_q[d] + ((a0 + a1) + (a2 + a3));
}

// ---------------- Fused kernel: GEMM + tanh·w + online softmax + z, one block per batch
// 512 threads = 16 warps, warp grid 2(m) x 8(n), warp tile m32 x n32.
__global__ __launch_bounds__(NTHR, 1)
void kFused(const float* __restrict__ input_q,
            const float* __restrict__ W_q,
            const float* __restrict__ wvec,
            const float* __restrict__ match_b,
            const int* __restrict__ mask_q,
            const float* __restrict__ input_p,
            float* __restrict__ out) {
    extern __shared__ uint32_t sh[];
    uint32_t* Wsh  = sh;                         // 256 x 128 words, swizzled bf16x2
    uint32_t* Qsh0 = sh + 32768;
    uint32_t* Qsh1 = Qsh0 + TT * QSTR;
    float* gpr_sh     = reinterpret_cast<float*>(Qsh1 + TT * QSTR);
    float* w_sh       = gpr_sh + DO_;
    float* e_sh       = w_sh + DO_;
    float* alpha_part = e_sh + TT;               // [64][8] partial row sums (also zbuf at end)
    float* red        = alpha_part + TT * 8;     // [0..1]=max, [2..3]=sum

    int b    = blockIdx.x;
    int tid  = threadIdx.x;
    int lane = tid & 31, wid = tid >> 5;
    int warp_m = wid & 1;        // 2 warps over 64 rows (32 each)
    int warp_n = wid >> 1;       // 8 warps over 256 cols (32 each)

    // ---- Load W_q (fp32) -> bf16 SMEM with 16B-chunk XOR swizzle
    for (int i = tid; i < 256 * 128; i += NTHR) {
        int n = i >> 7, kw = i & 127;
        float2 f = reinterpret_cast<const float2*>(W_q)[n * 128 + kw];
        __nv_bfloat162 h = __floats2bfloat162_rn(f.x, f.y);
        int chunk = kw >> 2;
        int phys  = chunk ^ (n & 7);
        Wsh[n * 128 + phys * 4 + (kw & 3)] = *reinterpret_cast<uint32_t*>(&h);
    }
    if (tid < DO_) {
        gpr_sh[tid] = g_gpr[b * DO_ + tid];
        w_sh[tid]   = wvec[tid];
    }

    const float   mb  = match_b[0];
    const float4* qb4 = reinterpret_cast<const float4*>(input_q + (size_t)b * T_ * DQ_);
    const int*    mqb = mask_q + (size_t)b * T_;

    // ---- Preload tile 0
    float4 pf[8];
#pragma unroll
    for (int j = 0; j < 8; ++j) pf[j] = qb4[tid + j * NTHR];
#pragma unroll
    for (int j = 0; j < 8; ++j) {
        int idx = tid + j * NTHR;
        int row = idx >> 6, c4 = idx & 63;
        __nv_bfloat162 h0 = __floats2bfloat162_rn(pf[j].x, pf[j].y);
        __nv_bfloat162 h1 = __floats2bfloat162_rn(pf[j].z, pf[j].w);
        Qsh0[row * QSTR + c4 * 2]     = *reinterpret_cast<uint32_t*>(&h0);
        Qsh0[row * QSTR + c4 * 2 + 1] = *reinterpret_cast<uint32_t*>(&h1);
    }
    __syncthreads();

    float M = -1e30f, S = 0.f, z = 0.f;
    int zd    = tid & 255;       // output dim this thread accumulates
    int zhalf = tid >> 8;        // which half of t-range
    int zword = zd >> 1, zhi = zd & 1;

    for (int it = 0; it < NTILES; ++it) {
        uint32_t* Qcur = (it & 1) ? Qsh1 : Qsh0;
        uint32_t* Qnxt = (it & 1) ? Qsh0 : Qsh1;
        int t0 = it * TT;

        // ---- Prefetch next tile into registers
        bool has_next = (it + 1 < NTILES);
        if (has_next) {
            const float4* src = qb4 + (size_t)(t0 + TT) * 64;
#pragma unroll
            for (int j = 0; j < 8; ++j) pf[j] = src[tid + j * NTHR];
        }

        // ---- MMA: C[64 x 256] = Qtile @ W^T, warp tile m32 x n32
        float c[8][4];
#pragma unroll
        for (int q = 0; q < 8; ++q) { c[q][0] = c[q][1] = c[q][2] = c[q][3] = 0.f; }

#pragma unroll 4
        for (int kc = 0; kc < 16; ++kc) {
            uint32_t a[2][4];
#pragma unroll
            for (int mt = 0; mt < 2; ++mt) {
                int arow = warp_m * 32 + mt * 16 + (lane & 15);
                int acol = kc * 8 + ((lane & 16) ? 4 : 0);
                uint32_t aaddr = (uint32_t)__cvta_generic_to_shared(&Qcur[arow * QSTR + acol]);
                asm volatile("ldmatrix.sync.aligned.m8n8.x4.shared.b16 {%0,%1,%2,%3}, [%4];"
                             : "=r"(a[mt][0]), "=r"(a[mt][1]), "=r"(a[mt][2]), "=r"(a[mt][3])
                             : "r"(aaddr));
            }
#pragma unroll
            for (int np = 0; np < 2; ++np) {
                int row   = warp_n * 32 + np * 16 + (lane & 7) + ((lane & 16) ? 8 : 0);
                int chunk = kc * 2 + ((lane & 8) ? 1 : 0);
                int phys  = chunk ^ (row & 7);
                uint32_t baddr = (uint32_t)__cvta_generic_to_shared(&Wsh[row * 128 + phys * 4]);
                uint32_t b0, b1, b2, b3;
                asm volatile("ldmatrix.sync.aligned.m8n8.x4.shared.b16 {%0,%1,%2,%3}, [%4];"
                             : "=r"(b0), "=r"(b1), "=r"(b2), "=r"(b3) : "r"(baddr));
#pragma unroll
                for (int mt = 0; mt < 2; ++mt) {
                    float* c0 = c[mt * 4 + np * 2];
                    float* c1 = c[mt * 4 + np * 2 + 1];
                    asm volatile(
                        "mma.sync.aligned.m16n8k16.row.col.f32.bf16.bf16.f32 "
                        "{%0,%1,%2,%3}, {%4,%5,%6,%7}, {%8,%9}, {%0,%1,%2,%3};"
                        : "+f"(c0[0]), "+f"(c0[1]), "+f"(c0[2]), "+f"(c0[3])
                        : "r"(a[mt][0]), "r"(a[mt][1]), "r"(a[mt][2]), "r"(a[mt][3]),
                          "r"(b0), "r"(b1));
                    asm volatile(
                        "mma.sync.aligned.m16n8k16.row.col.f32.bf16.bf16.f32 "
                        "{%0,%1,%2,%3}, {%4,%5,%6,%7}, {%8,%9}, {%0,%1,%2,%3};"
                        : "+f"(c1[0]), "+f"(c1[1]), "+f"(c1[2]), "+f"(c1[3])
                        : "r"(a[mt][0]), "r"(a[mt][1]), "r"(a[mt][2]), "r"(a[mt][3]),
                          "r"(b2), "r"(b3));
                }
            }
        }

        // ---- Store prefetched tile now (ends pf live range; Qnxt has no readers here)
        if (has_next) {
#pragma unroll
            for (int j = 0; j < 8; ++j) {
                int idx = tid + j * NTHR;
                int row = idx >> 6, c4 = idx & 63;
                __nv_bfloat162 h0 = __floats2bfloat162_rn(pf[j].x, pf[j].y);
                __nv_bfloat162 h1 = __floats2bfloat162_rn(pf[j].z, pf[j].w);
                Qnxt[row * QSTR + c4 * 2]     = *reinterpret_cast<uint32_t*>(&h0);
                Qnxt[row * QSTR + c4 * 2 + 1] = *reinterpret_cast<uint32_t*>(&h1);
            }
        }

        // ---- Epilogue: tanh + dot(w), quad-shfl reduce, leaders write disjoint partials
#pragma unroll
        for (int mt = 0; mt < 2; ++mt) {
            float p0 = 0.f, p1 = 0.f;
#pragma unroll
            for (int np = 0; np < 2; ++np) {
#pragma unroll
                for (int j = 0; j < 2; ++j) {
                    int n = warp_n * 32 + np * 16 + j * 8 + (lane & 3) * 2;
                    float g0 = gpr_sh[n], g1 = gpr_sh[n + 1];
                    float w0 = w_sh[n],   w1 = w_sh[n + 1];
                    float* cc = c[mt * 4 + np * 2 + j];
                    p0 += w0 * fast_tanh(cc[0] + g0) + w1 * fast_tanh(cc[1] + g1);
                    p1 += w0 * fast_tanh(cc[2] + g0) + w1 * fast_tanh(cc[3] + g1);
                }
            }
            // reduce across the quad (lane&3)
            p0 += __shfl_xor_sync(0xffffffffu, p0, 1);
            p0 += __shfl_xor_sync(0xffffffffu, p0, 2);
            p1 += __shfl_xor_sync(0xffffffffu, p1, 1);
            p1 += __shfl_xor_sync(0xffffffffu, p1, 2);
            if ((lane & 3) == 0) {
                int row0 = warp_m * 32 + mt * 16 + (lane >> 2);
                alpha_part[row0 * 8 + warp_n]       = p0;
                alpha_part[(row0 + 8) * 8 + warp_n] = p1;
            }
        }
        __syncthreads();   // S1: partials done, Qcur MMA reads done

        // ---- Stage 1: row sums, clip/mask, tile max
        float x = 0.f, mflt = 0.f;
        if (tid < TT) {
            const float* ap = &alpha_part[tid * 8];
            float raw = ((ap[0] + ap[1]) + (ap[2] + ap[3])) +
                        ((ap[4] + ap[5]) + (ap[6] + ap[7])) + mb;
            mflt = (float)mqb[t0 + tid];
            x = fminf(fmaxf(raw, -15.f), 15.f) * mflt;
            float wmx = x;
#pragma unroll
            for (int o = 16; o; o >>= 1) wmx = fmaxf(wmx, __shfl_xor_sync(0xffffffffu, wmx, o));
            if (lane == 0) red[wid] = wmx;
        }
        __syncthreads();   // S2

        float Mnew  = fmaxf(M, fmaxf(red[0], red[1]));
        float scale = expf(M - Mnew);
        M = Mnew;

        // ---- Stage 2: exponentials + tile sum
        if (tid < TT) {
            float e = expf(x - Mnew) * mflt;
            e_sh[tid] = e;
            float wsm = e;
#pragma unroll
            for (int o = 16; o; o >>= 1) wsm += __shfl_xor_sync(0xffffffffu, wsm, o);
            if (lane == 0) red[2 + wid] = wsm;
        }
        __syncthreads();   // S3

        S = S * scale + (red[2] + red[3]);

        // ---- z update: each thread owns (d = tid&255, half of t range)
        {
            float acc = 0.f;
            int tbase = zhalf * 32;
#pragma unroll 8
            for (int t = 0; t < 32; ++t) {
                uint32_t qw = Qcur[(tbase + t) * QSTR + zword];
                __nv_bfloat162 h2 = *reinterpret_cast<__nv_bfloat162*>(&qw);
                float qv = zhi ? __bfloat162float(__high2bfloat16(h2))
                               : __bfloat162float(__low2bfloat16(h2));
                acc += e_sh[tbase + t] * qv;
            }
            z = z * scale + acc;
        }
        __syncthreads();   // S4: Qcur free for next STS, e_sh free
    }

    // ---- Combine the two t-halves of z, then write out = [input_p | z/(S+1e-6)]
    alpha_part[tid] = z;          // 512 floats, reuse alpha_part
    __syncthreads();
    if (tid < DQ_) {
        float ztot = alpha_part[tid] + alpha_part[tid + 256];
        float inv  = 1.f / (S + 1e-6f);
        out[b * (DP_ + DQ_) + tid]       = input_p[b * DP_ + tid];
        out[b * (DP_ + DQ_) + DP_ + tid] = ztot * inv;
    }
}

extern "C" void kernel_launch(void* const* d_in, const int* in_sizes, int n_in,
                              void* d_out, int out_size) {
    const float* input_p = (const float*)d_in[0];
    const float* input_q = (const float*)d_in[2];
    const int*   mask_q  = (const int*)d_in[3];
    const float* h_tm1   = (const float*)d_in[4];
    const float* W_p_r   = (const float*)d_in[5];
    const float* b_p_r   = (const float*)d_in[6];
    const float* W_q     = (const float*)d_in[7];
    const float* b_q     = (const float*)d_in[8];
    const float* wv      = (const float*)d_in[9];
    const float* match_b = (const float*)d_in[10];
    float* out = (float*)d_out;

    kA_gpr<<<B_, 256>>>(input_p, h_tm1, W_p_r, b_p_r, b_q);

    size_t smemF = (size_t)(32768 + 2 * TT * QSTR) * 4 +
                   (DO_ + DO_ + TT + TT * 8 + 4) * 4;
    cudaFuncSetAttribute(kFused, cudaFuncAttributeMaxDynamicSharedMemorySize, (int)smemF);
    kFused<<<B_, NTHR, smemF>>>(input_q, W_q, wv, match_b, mask_q, input_p, out);
}

// round 5
// speedup vs baseline: 2.0180x; 1.1406x over previous
#include <cuda_runtime.h>
#include <cuda_bf16.h>
#include <cstdint>

#define B_ 128
#define T_ 2048
#define DP_ 256
#define DQ_ 256
#define DO_ 256
#define TT 64          // token tile
#define NTILES (T_ / TT)
#define QSTR 132       // Q smem row stride in 32-bit words
#define NTHR 512

__device__ float g_gpr[B_ * DO_];

__device__ __forceinline__ float fast_tanh(float x) {
    float y;
    asm("tanh.approx.f32 %0, %1;" : "=f"(y) : "f"(x));
    return y;
}

// ---------------- Kernel A: gpr[b,d] = cat(p,h)[b] . W_p_r[d] + b_p_r[d] + b_q[d]
__global__ void kA_gpr(const float* __restrict__ input_p,
                       const float* __restrict__ h_tm1,
                       const float* __restrict__ W_p_r,
                       const float* __restrict__ b_p_r,
                       const float* __restrict__ b_q) {
    __shared__ float ph[DP_ + DO_];
    int b = blockIdx.x, tid = threadIdx.x;
    ph[tid]       = input_p[b * DP_ + tid];
    ph[DP_ + tid] = h_tm1[b * DO_ + tid];
    __syncthreads();
    const float4* Wrow = reinterpret_cast<const float4*>(W_p_r + (size_t)tid * (DP_ + DO_));
    float a0 = 0.f, a1 = 0.f, a2 = 0.f, a3 = 0.f;
#pragma unroll 8
    for (int k4 = 0; k4 < (DP_ + DO_) / 4; ++k4) {
        float4 wv = Wrow[k4];
        a0 += wv.x * ph[k4 * 4 + 0];
        a1 += wv.y * ph[k4 * 4 + 1];
        a2 += wv.z * ph[k4 * 4 + 2];
        a3 += wv.w * ph[k4 * 4 + 3];
    }
    g_gpr[b * DO_ + tid] = b_p_r[tid] + b_q[tid] + ((a0 + a1) + (a2 + a3));
}

// ---------------- Fused kernel: GEMM + tanh·w + fixed-shift softmax + z
// 512 threads = 16 warps, warp grid 2(m) x 8(n), warp tile m32 x n32.
__global__ __launch_bounds__(NTHR, 1)
void kFused(const float* __restrict__ input_q,
            const float* __restrict__ W_q,
            const float* __restrict__ wvec,
            const float* __restrict__ match_b,
            const int* __restrict__ mask_q,
            const float* __restrict__ input_p,
            float* __restrict__ out) {
    extern __shared__ uint32_t sh[];
    uint32_t* Wsh  = sh;                         // 256 x 128 words, swizzled bf16x2
    uint32_t* Qsh0 = sh + 32768;
    uint32_t* Qsh1 = Qsh0 + TT * QSTR;
    float2* wg_sh      = reinterpret_cast<float2*>(Qsh1 + TT * QSTR);   // {w[d], gpr[d]}
    float*  e_sh       = reinterpret_cast<float*>(wg_sh + DO_);         // 64
    float*  alpha_part = e_sh + TT;                                     // [64][8]
    float*  red        = alpha_part + TT * 8;                           // 8
    float*  zbuf       = red + 8;                                       // [4][256]

    int b    = blockIdx.x;
    int tid  = threadIdx.x;
    int lane = tid & 31, wid = tid >> 5;
    int warp_m = wid & 1;        // 2 warps over 64 rows (32 each)
    int warp_n = wid >> 1;       // 8 warps over 256 cols (32 each)

    // ---- Load W_q (fp32) -> bf16 SMEM with 16B-chunk XOR swizzle
    for (int i = tid; i < 256 * 128; i += NTHR) {
        int n = i >> 7, kw = i & 127;
        float2 f = reinterpret_cast<const float2*>(W_q)[n * 128 + kw];
        __nv_bfloat162 h = __floats2bfloat162_rn(f.x, f.y);
        int chunk = kw >> 2;
        int phys  = chunk ^ (n & 7);
        Wsh[n * 128 + phys * 4 + (kw & 3)] = *reinterpret_cast<uint32_t*>(&h);
    }
    if (tid < DO_) wg_sh[tid] = make_float2(wvec[tid], g_gpr[b * DO_ + tid]);

    const float   mb  = match_b[0];
    const float4* qb4 = reinterpret_cast<const float4*>(input_q + (size_t)b * T_ * DQ_);
    const int*    mqb = mask_q + (size_t)b * T_;

    // ---- Preload tile 0
    float4 pf[8];
#pragma unroll
    for (int j = 0; j < 8; ++j) pf[j] = qb4[tid + j * NTHR];
#pragma unroll
    for (int j = 0; j < 8; ++j) {
        int idx = tid + j * NTHR;
        int row = idx >> 6, c4 = idx & 63;
        __nv_bfloat162 h0 = __floats2bfloat162_rn(pf[j].x, pf[j].y);
        __nv_bfloat162 h1 = __floats2bfloat162_rn(pf[j].z, pf[j].w);
        Qsh0[row * QSTR + c4 * 2]     = *reinterpret_cast<uint32_t*>(&h0);
        Qsh0[row * QSTR + c4 * 2 + 1] = *reinterpret_cast<uint32_t*>(&h1);
    }
    __syncthreads();

    // fixed-shift softmax state (no rescaling needed: x <= 15 always)
    float Sth = 0.f, Mth = -1e30f;     // owned by threads tid<64
    float z0 = 0.f, z1 = 0.f;
    int zq = wid >> 2;                 // t-quarter (16 tokens each)
    int d0 = (tid & 127) * 2;          // this thread's output dims {d0, d0+1}
    int zword = tid & 127;

    for (int it = 0; it < NTILES; ++it) {
        uint32_t* Qcur = (it & 1) ? Qsh1 : Qsh0;
        uint32_t* Qnxt = (it & 1) ? Qsh0 : Qsh1;
        int t0 = it * TT;

        // ---- prefetch: mask words for THIS tile + Q for next tile
        int mreg = mqb[t0 + (tid & 63)];
        bool has_next = (it + 1 < NTILES);
        if (has_next) {
            const float4* src = qb4 + (size_t)(t0 + TT) * 64;
#pragma unroll
            for (int j = 0; j < 8; ++j) pf[j] = src[tid + j * NTHR];
        }

        // ---- MMA: C[64 x 256] = Qtile @ W^T, warp tile m32 x n32
        float c[8][4];
#pragma unroll
        for (int q = 0; q < 8; ++q) { c[q][0] = c[q][1] = c[q][2] = c[q][3] = 0.f; }

#pragma unroll 4
        for (int kc = 0; kc < 16; ++kc) {
            uint32_t a[2][4];
#pragma unroll
            for (int mt = 0; mt < 2; ++mt) {
                int arow = warp_m * 32 + mt * 16 + (lane & 15);
                int acol = kc * 8 + ((lane & 16) ? 4 : 0);
                uint32_t aaddr = (uint32_t)__cvta_generic_to_shared(&Qcur[arow * QSTR + acol]);
                asm volatile("ldmatrix.sync.aligned.m8n8.x4.shared.b16 {%0,%1,%2,%3}, [%4];"
                             : "=r"(a[mt][0]), "=r"(a[mt][1]), "=r"(a[mt][2]), "=r"(a[mt][3])
                             : "r"(aaddr));
            }
#pragma unroll
            for (int np = 0; np < 2; ++np) {
                int row   = warp_n * 32 + np * 16 + (lane & 7) + ((lane & 16) ? 8 : 0);
                int chunk = kc * 2 + ((lane & 8) ? 1 : 0);
                int phys  = chunk ^ (row & 7);
                uint32_t baddr = (uint32_t)__cvta_generic_to_shared(&Wsh[row * 128 + phys * 4]);
                uint32_t b0, b1, b2, b3;
                asm volatile("ldmatrix.sync.aligned.m8n8.x4.shared.b16 {%0,%1,%2,%3}, [%4];"
                             : "=r"(b0), "=r"(b1), "=r"(b2), "=r"(b3) : "r"(baddr));
#pragma unroll
                for (int mt = 0; mt < 2; ++mt) {
                    float* c0 = c[mt * 4 + np * 2];
                    float* c1 = c[mt * 4 + np * 2 + 1];
                    asm volatile(
                        "mma.sync.aligned.m16n8k16.row.col.f32.bf16.bf16.f32 "
                        "{%0,%1,%2,%3}, {%4,%5,%6,%7}, {%8,%9}, {%0,%1,%2,%3};"
                        : "+f"(c0[0]), "+f"(c0[1]), "+f"(c0[2]), "+f"(c0[3])
                        : "r"(a[mt][0]), "r"(a[mt][1]), "r"(a[mt][2]), "r"(a[mt][3]),
                          "r"(b0), "r"(b1));
                    asm volatile(
                        "mma.sync.aligned.m16n8k16.row.col.f32.bf16.bf16.f32 "
                        "{%0,%1,%2,%3}, {%4,%5,%6,%7}, {%8,%9}, {%0,%1,%2,%3};"
                        : "+f"(c1[0]), "+f"(c1[1]), "+f"(c1[2]), "+f"(c1[3])
                        : "r"(a[mt][0]), "r"(a[mt][1]), "r"(a[mt][2]), "r"(a[mt][3]),
                          "r"(b2), "r"(b3));
                }
            }
        }

        // ---- store prefetched tile into other buffer (its last readers finished
        //      before S3 of the previous iteration)
        if (has_next) {
#pragma unroll
            for (int j = 0; j < 8; ++j) {
                int idx = tid + j * NTHR;
                int row = idx >> 6, c4 = idx & 63;
                __nv_bfloat162 h0 = __floats2bfloat162_rn(pf[j].x, pf[j].y);
                __nv_bfloat162 h1 = __floats2bfloat162_rn(pf[j].z, pf[j].w);
                Qnxt[row * QSTR + c4 * 2]     = *reinterpret_cast<uint32_t*>(&h0);
                Qnxt[row * QSTR + c4 * 2 + 1] = *reinterpret_cast<uint32_t*>(&h1);
            }
        }

        // ---- epilogue: tanh + dot(w), quad reduce, disjoint partial writes
#pragma unroll
        for (int mt = 0; mt < 2; ++mt) {
            float p0 = 0.f, p1 = 0.f;
#pragma unroll
            for (int np = 0; np < 2; ++np) {
#pragma unroll
                for (int j = 0; j < 2; ++j) {
                    int n = warp_n * 32 + np * 16 + j * 8 + (lane & 3) * 2;
                    float4 wg = *reinterpret_cast<const float4*>(&wg_sh[n]);   // {w0,g0,w1,g1}
                    float* cc = c[mt * 4 + np * 2 + j];
                    p0 += wg.x * fast_tanh(cc[0] + wg.y) + wg.z * fast_tanh(cc[1] + wg.w);
                    p1 += wg.x * fast_tanh(cc[2] + wg.y) + wg.z * fast_tanh(cc[3] + wg.w);
                }
            }
            p0 += __shfl_xor_sync(0xffffffffu, p0, 1);
            p0 += __shfl_xor_sync(0xffffffffu, p0, 2);
            p1 += __shfl_xor_sync(0xffffffffu, p1, 1);
            p1 += __shfl_xor_sync(0xffffffffu, p1, 2);
            if ((lane & 3) == 0) {
                int row0 = warp_m * 32 + mt * 16 + (lane >> 2);
                alpha_part[row0 * 8 + warp_n]       = p0;
                alpha_part[(row0 + 8) * 8 + warp_n] = p1;
            }
        }
        __syncthreads();   // S1: alpha partials ready

        // ---- stage 1 (threads 0..63): e = exp(x-15)*m ; accumulate S, M per-thread
        if (tid < TT) {
            const float* ap = &alpha_part[tid * 8];
            float raw = ((ap[0] + ap[1]) + (ap[2] + ap[3])) +
                        ((ap[4] + ap[5]) + (ap[6] + ap[7])) + mb;
            float mflt = (float)mreg;
            float x = fminf(fmaxf(raw, -15.f), 15.f) * mflt;
            float e = __expf(x - 15.f) * mflt;
            e_sh[tid] = e;
            Sth += e;
            Mth = fmaxf(Mth, x);
        }
        __syncthreads();   // S2: e_sh ready

        // ---- z update: thread owns dims {d0,d0+1}, t-quarter zq (16 tokens)
        {
            float a0 = 0.f, a1 = 0.f;
            int tbase = zq * 16;
#pragma unroll
            for (int ttk = 0; ttk < 16; ++ttk) {
                int t = tbase + ttk;
                uint32_t qw = Qcur[t * QSTR + zword];
                __nv_bfloat162 h2 = *reinterpret_cast<__nv_bfloat162*>(&qw);
                float e = e_sh[t];
                a0 += e * __bfloat162float(__low2bfloat16(h2));
                a1 += e * __bfloat162float(__high2bfloat16(h2));
            }
            z0 += a0;
            z1 += a1;
        }
        __syncthreads();   // S3: Qcur reads done; alpha_part/e_sh free; Qnxt visible
    }

    // ---- final reductions: S' and Mg over the 64 stage-1 threads
    if (tid < TT) {
        float s = Sth, m = Mth;
#pragma unroll
        for (int o = 16; o; o >>= 1) {
            s += __shfl_xor_sync(0xffffffffu, s, o);
            m = fmaxf(m, __shfl_xor_sync(0xffffffffu, m, o));
        }
        if (lane == 0) { red[wid * 2] = s; red[wid * 2 + 1] = m; }
    }
    zbuf[zq * 256 + d0]     = z0;
    zbuf[zq * 256 + d0 + 1] = z1;
    __syncthreads();

    if (tid < DQ_) {
        float Sp = red[0] + red[2];
        float Mg = fmaxf(red[1], red[3]);
        float denom = Sp + 1e-6f * __expf(Mg - 15.f);
        float zt = (zbuf[tid] + zbuf[256 + tid]) + (zbuf[512 + tid] + zbuf[768 + tid]);
        out[b * (DP_ + DQ_) + tid]       = input_p[b * DP_ + tid];
        out[b * (DP_ + DQ_) + DP_ + tid] = zt / denom;
    }
}

extern "C" void kernel_launch(void* const* d_in, const int* in_sizes, int n_in,
                              void* d_out, int out_size) {
    const float* input_p = (const float*)d_in[0];
    const float* input_q = (const float*)d_in[2];
    const int*   mask_q  = (const int*)d_in[3];
    const float* h_tm1   = (const float*)d_in[4];
    const float* W_p_r   = (const float*)d_in[5];
    const float* b_p_r   = (const float*)d_in[6];
    const float* W_q     = (const float*)d_in[7];
    const float* b_q     = (const float*)d_in[8];
    const float* wv      = (const float*)d_in[9];
    const float* match_b = (const float*)d_in[10];
    float* out = (float*)d_out;

    kA_gpr<<<B_, 256>>>(input_p, h_tm1, W_p_r, b_p_r, b_q);

    size_t smemF = (size_t)(32768 + 2 * TT * QSTR) * 4 +
                   (size_t)(DO_ * 2 + TT + TT * 8 + 8 + 1024) * 4;
    cudaFuncSetAttribute(kFused, cudaFuncAttributeMaxDynamicSharedMemorySize, (int)smemF);
    kFused<<<B_, NTHR, smemF>>>(input_q, W_q, wv, match_b, mask_q, input_p, out);
}